// round 9
// baseline (speedup 1.0000x reference)
#include <cuda_runtime.h>
#include <cstdint>

#define BB  2
#define SS  2048
#define DD  1024
#define HH  16
#define DHH 64

// Scratch (allocation-free rule: __device__ globals)
__device__ float g_QH[BB*HH*SS*DHH];   // [B,H,S,DH]
__device__ float g_KH[BB*HH*SS*DHH];   // [B,H,S,DH]
__device__ float g_VT[BB*HH*DHH*SS];   // [B,H,DH,S]  (transposed V)
__device__ float g_O [BB*SS*DD];       // [B,S,D]

// ---------------------------------------------------------------------------
__device__ __forceinline__ unsigned f2tf(float f) {
    unsigned u;
    asm("cvt.rna.tf32.f32 %0, %1;" : "=r"(u) : "f"(f));
    return u;
}

__device__ __forceinline__ void mma8(float c[4],
                                     unsigned a0, unsigned a1, unsigned a2, unsigned a3,
                                     unsigned b0, unsigned b1) {
    asm("mma.sync.aligned.m16n8k8.row.col.f32.tf32.tf32.f32 "
        "{%0,%1,%2,%3},{%4,%5,%6,%7},{%8,%9},{%0,%1,%2,%3};"
        : "+f"(c[0]), "+f"(c[1]), "+f"(c[2]), "+f"(c[3])
        : "r"(a0), "r"(a1), "r"(a2), "r"(a3), "r"(b0), "r"(b1));
}

// ===========================================================================
// FUSED ATTENTION: scores + softmax + PV in one kernel (2-pass recompute).
// Block: 128 rows x full 2048 cols of one (b,h). 256 threads.
// Warp layout: wm = warp&1 (64 rows), wn = warp>>1 (16 cols), mt=4, nt=2.
//
// Dynamic smem layout (bytes):
//   [0      ) QA planes  unsigned[4][8][8][32]   32768   (Q 128x64, resident)
//   [32768  ) KB planes  unsigned[2][8][8][32]   16384   (K tile 64x64)
//   [49152  ) VB planes  unsigned[2][8][8][32]   16384   (V^T tile 64x64)
//   [65536  ) Ps         unsigned[128][68]       34816   (tf32 P tile; pass2)
//            red (overlay on Ps)  float2[4][128]  4096   (pass1 stats partials)
//   [100352 ) sF         float2[128]              1024   (final m, 1/s per row)
// total 101376; 2 CTAs/SM (202.8 KB <= 228 KB)
// ===========================================================================
#define SMEM_FUSED 101376

__global__ __launch_bounds__(256, 2) void fused_attn_kernel(
    const int* __restrict__ mask, float* __restrict__ attn)
{
    extern __shared__ char sm_raw[];
    unsigned (*QA)[8][8][32] = (unsigned (*)[8][8][32])(sm_raw);
    unsigned (*KB)[8][8][32] = (unsigned (*)[8][8][32])(sm_raw + 32768);
    unsigned (*VB)[8][8][32] = (unsigned (*)[8][8][32])(sm_raw + 49152);
    unsigned* Ps  = (unsigned*)(sm_raw + 65536);     // [128][68]
    float2*   red = (float2*)  (sm_raw + 65536);     // overlay, [wn*128 + lr]
    float2*   sF  = (float2*)  (sm_raw + 100352);    // [128]

    const int tid  = threadIdx.x;
    const int lane = tid & 31;
    const int warp = tid >> 5;
    const int wm = warp & 1;
    const int wn = warp >> 1;
    const int bh = blockIdx.y;
    const int m0 = blockIdx.x * 128;
    const float* Qg = g_QH + (size_t)bh * SS * DHH + (size_t)m0 * DHH;
    const float* Kg = g_KH + (size_t)bh * SS * DHH;
    const float* Vg = g_VT + (size_t)bh * DHH * SS;
    float* Cp = attn + (size_t)bh * SS * SS;

    // ---- load Q planes (128 x 64), resident for both passes ----
    {
        int r = tid >> 1, c0 = (tid & 1) << 5;
        const float* p = Qg + (size_t)r * DHH + c0;
        int g = r >> 4, rr = r & 15, Lb = (rr & 7) * 4, er = rr >> 3;
        #pragma unroll
        for (int i = 0; i < 8; i++) {
            float4 v = *(const float4*)(p + 4 * i);
            int c = c0 + 4 * i, ks = c >> 3, e = er + ((c & 4) >> 1);
            uint4 u = make_uint4(f2tf(v.x), f2tf(v.y), f2tf(v.z), f2tf(v.w));
            *(uint4*)&QA[e][g][ks][Lb] = u;
        }
    }

    // tile64 loader params (K and V^T tiles, 64x64)
    const int t64_r = tid >> 2, t64_c0 = (tid & 3) << 4;
    const int t64_g = t64_r >> 3, t64_Lb = (t64_r & 7) * 4;

    // ================= PASS 1: row stats (m, s) =================
    float mrow[8], srow[8];
    #pragma unroll
    for (int i = 0; i < 8; i++) { mrow[i] = -1e38f; srow[i] = 0.f; }

    #pragma unroll 1
    for (int kt = 0; kt < SS / 64; kt++) {
        __syncthreads();
        {   // load K tile (rows kt*64.., cols 0..63 of head dim)
            const float* p = Kg + (size_t)(kt * 64 + t64_r) * DHH + t64_c0;
            #pragma unroll
            for (int i = 0; i < 4; i++) {
                float4 v = *(const float4*)(p + 4 * i);
                int c = t64_c0 + 4 * i, ks = c >> 3, e = (c & 4) >> 2;
                uint4 u = make_uint4(f2tf(v.x), f2tf(v.y), f2tf(v.z), f2tf(v.w));
                *(uint4*)&KB[e][t64_g][ks][t64_Lb] = u;
            }
        }
        __syncthreads();

        float acc[4][2][4] = {};
        #pragma unroll
        for (int ks = 0; ks < 8; ks++) {
            unsigned a[4][4];
            #pragma unroll
            for (int mt = 0; mt < 4; mt++) {
                int g = wm * 4 + mt;
                a[mt][0] = QA[0][g][ks][lane]; a[mt][1] = QA[1][g][ks][lane];
                a[mt][2] = QA[2][g][ks][lane]; a[mt][3] = QA[3][g][ks][lane];
            }
            unsigned b[2][2];
            #pragma unroll
            for (int nt = 0; nt < 2; nt++) {
                int g = wn * 2 + nt;
                b[nt][0] = KB[0][g][ks][lane]; b[nt][1] = KB[1][g][ks][lane];
            }
            #pragma unroll
            for (int mt = 0; mt < 4; mt++)
                #pragma unroll
                for (int nt = 0; nt < 2; nt++)
                    mma8(acc[mt][nt], a[mt][0], a[mt][1], a[mt][2], a[mt][3],
                         b[nt][0], b[nt][1]);
        }

        // mask + scale + online update
        #pragma unroll
        for (int mt = 0; mt < 4; mt++) {
            int r_lo = m0 + wm * 64 + mt * 16 + (lane >> 2);
            int r_hi = r_lo + 8;
            float xl[4], xh[4];
            #pragma unroll
            for (int nt = 0; nt < 2; nt++) {
                int cn = kt * 64 + wn * 16 + nt * 8 + 2 * (lane & 3);
                int2 mm0 = *(const int2*)(mask + (size_t)r_lo * SS + cn);
                int2 mm1 = *(const int2*)(mask + (size_t)r_hi * SS + cn);
                xl[nt*2+0] = mm0.x ? acc[mt][nt][0] * 0.125f : -1e34f;
                xl[nt*2+1] = mm0.y ? acc[mt][nt][1] * 0.125f : -1e34f;
                xh[nt*2+0] = mm1.x ? acc[mt][nt][2] * 0.125f : -1e34f;
                xh[nt*2+1] = mm1.y ? acc[mt][nt][3] * 0.125f : -1e34f;
            }
            {   // row lo
                float tm = fmaxf(fmaxf(xl[0], xl[1]), fmaxf(xl[2], xl[3]));
                float mn = fmaxf(mrow[mt*2], tm);
                srow[mt*2] = srow[mt*2] * __expf(mrow[mt*2] - mn)
                    + __expf(xl[0]-mn) + __expf(xl[1]-mn)
                    + __expf(xl[2]-mn) + __expf(xl[3]-mn);
                mrow[mt*2] = mn;
            }
            {   // row hi
                float tm = fmaxf(fmaxf(xh[0], xh[1]), fmaxf(xh[2], xh[3]));
                float mn = fmaxf(mrow[mt*2+1], tm);
                srow[mt*2+1] = srow[mt*2+1] * __expf(mrow[mt*2+1] - mn)
                    + __expf(xh[0]-mn) + __expf(xh[1]-mn)
                    + __expf(xh[2]-mn) + __expf(xh[3]-mn);
                mrow[mt*2+1] = mn;
            }
        }
    }

    // ---- reduce stats: across the 4 lanes sharing each row ----
    #pragma unroll
    for (int o = 1; o <= 2; o <<= 1) {
        #pragma unroll
        for (int i = 0; i < 8; i++) {
            float om = __shfl_xor_sync(0xffffffffu, mrow[i], o);
            float os = __shfl_xor_sync(0xffffffffu, srow[i], o);
            float mn = fmaxf(mrow[i], om);
            srow[i] = srow[i] * __expf(mrow[i] - mn) + os * __expf(om - mn);
            mrow[i] = mn;
        }
    }
    __syncthreads();            // Ps region free; red overlay safe
    if ((lane & 3) == 0) {
        #pragma unroll
        for (int i = 0; i < 8; i++) {
            int lr = wm * 64 + (i >> 1) * 16 + (lane >> 2) + (i & 1) * 8;
            red[wn * 128 + lr] = make_float2(mrow[i], srow[i]);
        }
    }
    __syncthreads();
    // ---- merge the 4 wn partials; warps wn==0 publish final (m, 1/s) ----
    if (wn == 0 && (lane & 3) == 0) {
        #pragma unroll
        for (int i = 0; i < 8; i++) {
            int lr = wm * 64 + (i >> 1) * 16 + (lane >> 2) + (i & 1) * 8;
            float m = -1e38f, s = 0.f;
            #pragma unroll
            for (int w = 0; w < 4; w++) {
                float2 p = red[w * 128 + lr];
                float mn = fmaxf(m, p.x);
                s = s * __expf(m - mn) + p.y * __expf(p.x - mn);
                m = mn;
            }
            sF[lr] = make_float2(m, 1.0f / s);
        }
    }
    __syncthreads();

    // ================= PASS 2: p = exp(x-m)/s -> attn, O += P.V =================
    float oacc[4][2][4] = {};

    #pragma unroll 1
    for (int kt = 0; kt < SS / 64; kt++) {
        {   // load K tile
            const float* p = Kg + (size_t)(kt * 64 + t64_r) * DHH + t64_c0;
            #pragma unroll
            for (int i = 0; i < 4; i++) {
                float4 v = *(const float4*)(p + 4 * i);
                int c = t64_c0 + 4 * i, ks = c >> 3, e = (c & 4) >> 2;
                uint4 u = make_uint4(f2tf(v.x), f2tf(v.y), f2tf(v.z), f2tf(v.w));
                *(uint4*)&KB[e][t64_g][ks][t64_Lb] = u;
            }
        }
        {   // load V^T tile: rows = head dim (64), cols = seq kt*64..
            const float* p = Vg + (size_t)t64_r * SS + kt * 64 + t64_c0;
            #pragma unroll
            for (int i = 0; i < 4; i++) {
                float4 v = *(const float4*)(p + 4 * i);
                int c = t64_c0 + 4 * i, ks = c >> 3, e = (c & 4) >> 2;
                uint4 u = make_uint4(f2tf(v.x), f2tf(v.y), f2tf(v.z), f2tf(v.w));
                *(uint4*)&VB[e][t64_g][ks][t64_Lb] = u;
            }
        }
        __syncthreads();

        float acc[4][2][4] = {};
        #pragma unroll
        for (int ks = 0; ks < 8; ks++) {
            unsigned a[4][4];
            #pragma unroll
            for (int mt = 0; mt < 4; mt++) {
                int g = wm * 4 + mt;
                a[mt][0] = QA[0][g][ks][lane]; a[mt][1] = QA[1][g][ks][lane];
                a[mt][2] = QA[2][g][ks][lane]; a[mt][3] = QA[3][g][ks][lane];
            }
            unsigned b[2][2];
            #pragma unroll
            for (int nt = 0; nt < 2; nt++) {
                int g = wn * 2 + nt;
                b[nt][0] = KB[0][g][ks][lane]; b[nt][1] = KB[1][g][ks][lane];
            }
            #pragma unroll
            for (int mt = 0; mt < 4; mt++)
                #pragma unroll
                for (int nt = 0; nt < 2; nt++)
                    mma8(acc[mt][nt], a[mt][0], a[mt][1], a[mt][2], a[mt][3],
                         b[nt][0], b[nt][1]);
        }

        // p = exp(x - m) * inv_s; write attn (fp32) + Ps (tf32)
        #pragma unroll
        for (int mt = 0; mt < 4; mt++) {
            int lr_lo = wm * 64 + mt * 16 + (lane >> 2);
            int r_lo = m0 + lr_lo;
            int r_hi = r_lo + 8;
            float2 st0 = sF[lr_lo];
            float2 st1 = sF[lr_lo + 8];
            #pragma unroll
            for (int nt = 0; nt < 2; nt++) {
                int cl = wn * 16 + nt * 8 + 2 * (lane & 3);
                int cn = kt * 64 + cl;
                int2 mm0 = *(const int2*)(mask + (size_t)r_lo * SS + cn);
                int2 mm1 = *(const int2*)(mask + (size_t)r_hi * SS + cn);
                float x0 = mm0.x ? acc[mt][nt][0] * 0.125f : -1e34f;
                float x1 = mm0.y ? acc[mt][nt][1] * 0.125f : -1e34f;
                float x2 = mm1.x ? acc[mt][nt][2] * 0.125f : -1e34f;
                float x3 = mm1.y ? acc[mt][nt][3] * 0.125f : -1e34f;
                float p0 = __expf(x0 - st0.x) * st0.y;
                float p1 = __expf(x1 - st0.x) * st0.y;
                float p2 = __expf(x2 - st1.x) * st1.y;
                float p3 = __expf(x3 - st1.x) * st1.y;
                *(float2*)(Cp + (size_t)r_lo * SS + cn) = make_float2(p0, p1);
                *(float2*)(Cp + (size_t)r_hi * SS + cn) = make_float2(p2, p3);
                *(uint2*)&Ps[lr_lo * 68 + cl]       = make_uint2(f2tf(p0), f2tf(p1));
                *(uint2*)&Ps[(lr_lo + 8) * 68 + cl] = make_uint2(f2tf(p2), f2tf(p3));
            }
        }
        __syncthreads();

        // O += P . V   (A = Ps, conflict-free scalar LDS; B = VB planes)
        #pragma unroll
        for (int ks = 0; ks < 8; ks++) {
            unsigned a[4][4];
            #pragma unroll
            for (int mt = 0; mt < 4; mt++) {
                int R = wm * 64 + mt * 16 + (lane >> 2);
                int kk = ks * 8 + (lane & 3);
                a[mt][0] = Ps[R * 68 + kk];
                a[mt][1] = Ps[(R + 8) * 68 + kk];
                a[mt][2] = Ps[R * 68 + kk + 4];
                a[mt][3] = Ps[(R + 8) * 68 + kk + 4];
            }
            unsigned b[2][2];
            #pragma unroll
            for (int nt = 0; nt < 2; nt++) {
                int g = wn * 2 + nt;
                b[nt][0] = VB[0][g][ks][lane]; b[nt][1] = VB[1][g][ks][lane];
            }
            #pragma unroll
            for (int mt = 0; mt < 4; mt++)
                #pragma unroll
                for (int nt = 0; nt < 2; nt++)
                    mma8(oacc[mt][nt], a[mt][0], a[mt][1], a[mt][2], a[mt][3],
                         b[nt][0], b[nt][1]);
        }
        __syncthreads();
    }

    // ---- O epilogue -> g_O [B,S,D] ----
    const int b = bh >> 4, h = bh & 15;
    #pragma unroll
    for (int mt = 0; mt < 4; mt++) {
        int s_lo = m0 + wm * 64 + mt * 16 + (lane >> 2);
        int s_hi = s_lo + 8;
        #pragma unroll
        for (int nt = 0; nt < 2; nt++) {
            int n = wn * 16 + nt * 8 + 2 * (lane & 3);
            *(float2*)&g_O[((size_t)(b * SS + s_lo)) * DD + h * DHH + n] =
                make_float2(oacc[mt][nt][0], oacc[mt][nt][1]);
            *(float2*)&g_O[((size_t)(b * SS + s_hi)) * DD + h * DHH + n] =
                make_float2(oacc[mt][nt][2], oacc[mt][nt][3]);
        }
    }
}

// ===========================================================================
// GEMM core for projections / output (unchanged from R6)
// ===========================================================================
struct __align__(16) Smem {
    unsigned A[2][4][8][4][32];
    unsigned B[2][2][8][4][32];
};

__device__ __forceinline__ void stsA(Smem& S, int buf, int r, int cbase, const float4* v) {
    const int g    = r >> 4;
    const int rr   = r & 15;
    const int Lb   = (rr & 7) * 4;
    const int erow = rr >> 3;
    #pragma unroll
    for (int i = 0; i < 4; i++) {
        const int c  = cbase + 4 * i;
        const int ks = c >> 3;
        const int e  = erow + ((c & 4) >> 1);
        uint4 u;
        u.x = f2tf(v[i].x); u.y = f2tf(v[i].y); u.z = f2tf(v[i].z); u.w = f2tf(v[i].w);
        *(uint4*)&S.A[buf][e][g][ks][Lb] = u;
    }
}

__device__ __forceinline__ void stsB(Smem& S, int buf, int n, int cbase, const float4* v) {
    const int g  = n >> 3;
    const int Lb = (n & 7) * 4;
    #pragma unroll
    for (int i = 0; i < 2; i++) {
        const int c  = cbase + 4 * i;
        const int ks = c >> 3;
        const int e  = (c & 4) >> 2;
        uint4 u;
        u.x = f2tf(v[i].x); u.y = f2tf(v[i].y); u.z = f2tf(v[i].z); u.w = f2tf(v[i].w);
        *(uint4*)&S.B[buf][e][g][ks][Lb] = u;
    }
}

__device__ __forceinline__ void mma_step(const Smem& S, int buf, int lane, int wm, int wn,
                                         float (*acc)[2][4]) {
    #pragma unroll
    for (int ks = 0; ks < 4; ks++) {
        unsigned a[4][4];
        #pragma unroll
        for (int mt = 0; mt < 4; mt++) {
            const int g = wm * 4 + mt;
            a[mt][0] = S.A[buf][0][g][ks][lane];
            a[mt][1] = S.A[buf][1][g][ks][lane];
            a[mt][2] = S.A[buf][2][g][ks][lane];
            a[mt][3] = S.A[buf][3][g][ks][lane];
        }
        unsigned b[2][2];
        #pragma unroll
        for (int nt = 0; nt < 2; nt++) {
            const int g = wn * 2 + nt;
            b[nt][0] = S.B[buf][0][g][ks][lane];
            b[nt][1] = S.B[buf][1][g][ks][lane];
        }
        #pragma unroll
        for (int mt = 0; mt < 4; mt++)
            #pragma unroll
            for (int nt = 0; nt < 2; nt++)
                mma8(acc[mt][nt], a[mt][0], a[mt][1], a[mt][2], a[mt][3],
                     b[nt][0], b[nt][1]);
    }
}

template<int KB_>
__device__ __forceinline__ void gemm_core(
    const float* __restrict__ Ag, int lda,
    const float* __restrict__ Bg, int ldb,
    Smem& S, float (*acc)[2][4])
{
    const int tid  = threadIdx.x;
    const int lane = tid & 31;
    const int warp = tid >> 5;
    const int wm = warp & 1;
    const int wn = warp >> 1;

    const int ar = tid >> 1, ac = (tid & 1) << 4;
    const int br = tid >> 2, bc = (tid & 3) << 3;
    const float* Ap = Ag + (size_t)ar * lda + ac;
    const float* Bp = Bg + (size_t)br * ldb + bc;

    float4 aL[4], bL[2];
    #pragma unroll
    for (int i = 0; i < 4; i++) aL[i] = *(const float4*)(Ap + 4 * i);
    #pragma unroll
    for (int i = 0; i < 2; i++) bL[i] = *(const float4*)(Bp + 4 * i);
    stsA(S, 0, ar, ac, aL);
    stsB(S, 0, br, bc, bL);
    __syncthreads();

    #pragma unroll 2
    for (int kb = 1; kb < KB_; kb++) {
        #pragma unroll
        for (int i = 0; i < 4; i++) aL[i] = *(const float4*)(Ap + kb * 32 + 4 * i);
        #pragma unroll
        for (int i = 0; i < 2; i++) bL[i] = *(const float4*)(Bp + kb * 32 + 4 * i);
        mma_step(S, (kb - 1) & 1, lane, wm, wn, acc);
        stsA(S, kb & 1, ar, ac, aL);
        stsB(S, kb & 1, br, bc, bL);
        __syncthreads();
    }
    mma_step(S, (KB_ - 1) & 1, lane, wm, wn, acc);
}

// ---------------------------------------------------------------------------
__global__ __launch_bounds__(256, 2) void proj_kernel(
    const float* __restrict__ X, const float* __restrict__ W, int which)
{
    __shared__ Smem S;
    const int m0 = blockIdx.y * 128;
    const int n0 = blockIdx.x * 64;
    float acc[4][2][4] = {};
    gemm_core<DD/32>(X + (size_t)m0 * DD, DD, W + (size_t)n0 * DD, DD, S, acc);

    const int tid = threadIdx.x, lane = tid & 31, warp = tid >> 5;
    const int wm = warp & 1, wn = warp >> 1;
    #pragma unroll
    for (int mt = 0; mt < 4; mt++) {
        int m_lo = m0 + wm * 64 + mt * 16 + (lane >> 2);
        int m_hi = m_lo + 8;
        int b_lo = m_lo >> 11, s_lo = m_lo & (SS - 1);
        int b_hi = m_hi >> 11, s_hi = m_hi & (SS - 1);
        #pragma unroll
        for (int nt = 0; nt < 2; nt++) {
            int cn = n0 + wn * 16 + nt * 8 + 2 * (lane & 3);
            int h = cn >> 6, d = cn & 63;
            float c0 = acc[mt][nt][0], c1 = acc[mt][nt][1];
            float c2 = acc[mt][nt][2], c3 = acc[mt][nt][3];
            if (which == 2) {
                g_VT[((size_t)((b_lo*HH + h)*DHH + d    )) * SS + s_lo] = c0;
                g_VT[((size_t)((b_lo*HH + h)*DHH + d + 1)) * SS + s_lo] = c1;
                g_VT[((size_t)((b_hi*HH + h)*DHH + d    )) * SS + s_hi] = c2;
                g_VT[((size_t)((b_hi*HH + h)*DHH + d + 1)) * SS + s_hi] = c3;
            } else {
                float* dst = (which == 0) ? g_QH : g_KH;
                *(float2*)&dst[(((size_t)(b_lo*HH + h)*SS + s_lo) << 6) + d] = make_float2(c0, c1);
                *(float2*)&dst[(((size_t)(b_hi*HH + h)*SS + s_hi) << 6) + d] = make_float2(c2, c3);
            }
        }
    }
}

// ---------------------------------------------------------------------------
__global__ __launch_bounds__(256, 2) void out_kernel(
    const float* __restrict__ Wo, float* __restrict__ out)
{
    __shared__ Smem S;
    const int m0 = blockIdx.y * 128;
    const int n0 = blockIdx.x * 64;
    float acc[4][2][4] = {};
    gemm_core<DD/32>(g_O + (size_t)m0 * DD, DD, Wo + (size_t)n0 * DD, DD, S, acc);

    const int tid = threadIdx.x, lane = tid & 31, warp = tid >> 5;
    const int wm = warp & 1, wn = warp >> 1;
    #pragma unroll
    for (int mt = 0; mt < 4; mt++) {
        int m_lo = m0 + wm * 64 + mt * 16 + (lane >> 2);
        int m_hi = m_lo + 8;
        #pragma unroll
        for (int nt = 0; nt < 2; nt++) {
            int cn = n0 + wn * 16 + nt * 8 + 2 * (lane & 3);
            *(float2*)(out + (size_t)m_lo * DD + cn) =
                make_float2(acc[mt][nt][0], acc[mt][nt][1]);
            *(float2*)(out + (size_t)m_hi * DD + cn) =
                make_float2(acc[mt][nt][2], acc[mt][nt][3]);
        }
    }
}

// ---------------------------------------------------------------------------
extern "C" void kernel_launch(void* const* d_in, const int* in_sizes, int n_in,
                              void* d_out, int out_size)
{
    const float* q    = (const float*)d_in[0];
    const float* k    = (const float*)d_in[1];
    const float* v    = (const float*)d_in[2];
    const int*   mask = (const int*)  d_in[3];
    const float* Wq   = (const float*)d_in[4];
    const float* Wk   = (const float*)d_in[5];
    const float* Wv   = (const float*)d_in[6];
    const float* Wo   = (const float*)d_in[7];

    float* out  = (float*)d_out;
    float* attn = out + (size_t)BB * SS * DD;   // out first, then attn

    static int smem_set = 0;
    if (!smem_set) {
        cudaFuncSetAttribute(fused_attn_kernel,
                             cudaFuncAttributeMaxDynamicSharedMemorySize, SMEM_FUSED);
        smem_set = 1;
    }

    dim3 blk(256);
    dim3 gp(DD / 64, (BB * SS) / 128);          // 16 x 32
    proj_kernel<<<gp, blk>>>(q, Wq, 0);
    proj_kernel<<<gp, blk>>>(k, Wk, 1);
    proj_kernel<<<gp, blk>>>(v, Wv, 2);

    fused_attn_kernel<<<dim3(SS / 128, BB * HH), blk, SMEM_FUSED>>>(mask, attn);

    out_kernel<<<gp, blk>>>(Wo, out);
}